// round 13
// baseline (speedup 1.0000x reference)
#include <cuda_runtime.h>
#include <stdint.h>

#define DD 512
#define HH 8
#define MAXN 50048
#define MAXE 800000
#define MAXB 1024
#define LN_EPS 1e-5f
#define TPB 256

typedef unsigned long long u64;

// ---------------- scratch (device globals; zero-initialized at load) -----------
__device__ __align__(16) int   g_degi[MAXN];     // invariant: zero at call entry
__device__ __align__(16) float g_u   [MAXN * HH];   // raw x@W1
__device__ __align__(16) float g_agg1[MAXN * HH];
__device__ __align__(16) float g_v   [MAXN * HH];
__device__ __align__(16) float g_agg2[MAXN * HH];
__device__ __align__(16) int2  g_edge[MAXE];
// Flag-tree barrier state: monotonic epochs, never reset (graph-replay safe).
__device__ volatile unsigned g_flag[MAXB];
__device__ volatile unsigned g_rel;

// ---------------- helpers ------------------------------------------------------
__device__ __forceinline__ void red_add_v4(float* addr, float4 v) {
    asm volatile("red.global.add.v4.f32 [%0], {%1,%2,%3,%4};"
                 :: "l"(addr), "f"(v.x), "f"(v.y), "f"(v.z), "f"(v.w)
                 : "memory");
}

// packed f32x2 FMA: d = a*b + c on both 32-bit halves (1 issue slot, 2 FMAs)
__device__ __forceinline__ u64 ffma2(u64 a, u64 b, u64 c) {
    u64 d;
    asm("fma.rn.f32x2 %0, %1, %2, %3;" : "=l"(d) : "l"(a), "l"(b), "l"(c));
    return d;
}
__device__ __forceinline__ u64 fpack2(float v) {          // (v, v)
    u64 d; asm("mov.b64 %0, {%1, %1};" : "=l"(d) : "f"(v)); return d;
}
__device__ __forceinline__ float2 funpack2(u64 v) {
    float2 r; asm("mov.b64 {%0, %1}, %2;" : "=f"(r.x), "=f"(r.y) : "l"(v));
    return r;
}

// Flag-tree grid barrier: per-block flags (no same-address atomic pile-up),
// block 0 scans + publishes a single release word. Epochs are monotonic.
__device__ __forceinline__ void gsync(unsigned target, unsigned nb) {
    __syncthreads();
    if (blockIdx.x == 0) {
        if (threadIdx.x == 0) { __threadfence(); g_flag[0] = target; }
        for (unsigned i = threadIdx.x; i < nb; i += TPB)
            while ((int)(g_flag[i] - target) < 0) __nanosleep(32);
        __syncthreads();
        if (threadIdx.x == 0) { __threadfence(); g_rel = target; }
    } else {
        if (threadIdx.x == 0) {
            __threadfence();
            g_flag[blockIdx.x] = target;
            while ((int)(g_rel - target) < 0) __nanosleep(64);
            __threadfence();
        }
    }
    __syncthreads();
}

// ---------------- the single persistent kernel ---------------------------------
__global__ void __launch_bounds__(TPB, 4)
k_fused(const float* __restrict__ x,
        const float* __restrict__ sf,
        const float* __restrict__ W1,
        const float* __restrict__ b1,
        const float* __restrict__ gamma,
        const float* __restrict__ beta,
        const float* __restrict__ W2,
        const float* __restrict__ b2,
        const int*   __restrict__ ei,
        float* __restrict__ out,
        int N, int E, unsigned nb) {
    const int tid   = threadIdx.x;
    const int gtid  = blockIdx.x * TPB + tid;
    const int T     = gridDim.x * TPB;
    const int lane  = tid & 31;
    const int gwarp = gtid >> 5;
    const int W     = T >> 5;

    // Phase A: W1 transposed, s_w[h*DD + c] (16 KB). Phase F: W2 | b2 (18 KB).
    __shared__ float s_w[DD * HH + DD];
    __shared__ int   s_is64;
    __shared__ unsigned s_base;

    // ---- prologue: stage W1 transposed + detection + barrier epoch base ----
    for (int i = tid; i < DD * HH; i += TPB) {
        int c = i >> 3, h = i & 7;           // W1 is [DD][HH] row-major
        s_w[h * DD + c] = W1[i];
    }
    if (tid == 0) {
        int f = 1;
        int lim = 2 * E < 32 ? 2 * E : 32;
        for (int w = 1; w < lim; w += 2)
            if (ei[w] != 0) { f = 0; break; }
        s_is64 = f;
        s_base = g_flag[blockIdx.x];   // own flag: all blocks equal at entry
    }
    __syncthreads();
    const unsigned base = s_base;

    // ================= Phase A: edge prep + raw GEMM1 (independent) ==========
    {
        const int is64 = s_is64;
        for (int e = gtid; e < E; e += T) {
            int src, dst;
            if (is64) {
                src = ((const int2*)ei)[e].x;
                dst = ((const int2*)ei)[(size_t)E + e].x;
            } else {
                src = ei[e];
                dst = ei[E + e];
            }
            g_edge[e] = make_int2(src, dst);
            atomicAdd(&g_degi[dst], 1);
        }
    }
    // raw u = x @ W1; warp per 2 nodes; prefetched LDG.128, f32x2 FMAs
    for (int n0 = gwarp * 2; n0 < N; n0 += W * 2) {
        const int  n1   = n0 + 1;
        const bool has1 = (n1 < N);
        const ulonglong2* x0 = (const ulonglong2*)(x + (size_t)n0 * DD);
        const ulonglong2* x1 = (const ulonglong2*)(x + (size_t)(has1 ? n1 : n0) * DD);
        u64 acc0[HH], acc1[HH];
#pragma unroll
        for (int h = 0; h < HH; h++) { acc0[h] = 0ull; acc1[h] = 0ull; }

        ulonglong2 pa = __ldcs(&x0[lane]);
        ulonglong2 pb = __ldcs(&x1[lane]);
#pragma unroll
        for (int it = 0; it < 4; it++) {
            ulonglong2 xv0 = pa, xv1 = pb;
            if (it < 3) {                       // prefetch next tile
                pa = __ldcs(&x0[lane + (it + 1) * 32]);
                pb = __ldcs(&x1[lane + (it + 1) * 32]);
            }
            int c4 = lane + it * 32;
#pragma unroll
            for (int h = 0; h < HH; h++) {
                ulonglong2 w = *((const ulonglong2*)(s_w + h * DD) + c4); // LDS.128
                acc0[h] = ffma2(xv0.x, w.x, acc0[h]);
                acc0[h] = ffma2(xv0.y, w.y, acc0[h]);
                acc1[h] = ffma2(xv1.x, w.x, acc1[h]);
                acc1[h] = ffma2(xv1.y, w.y, acc1[h]);
            }
        }
        // horizontal: pair-sum, 1 full butterfly, split nodes across half-warps
        float t[HH];
#pragma unroll
        for (int h = 0; h < HH; h++) {
            float2 p0 = funpack2(acc0[h]);
            float2 p1 = funpack2(acc1[h]);
            float s0 = p0.x + p0.y, s1 = p1.x + p1.y;
            s0 += __shfl_xor_sync(0xffffffffu, s0, 16);
            s1 += __shfl_xor_sync(0xffffffffu, s1, 16);
            t[h] = (lane & 16) ? s1 : s0;
        }
#pragma unroll
        for (int off = 8; off; off >>= 1)
#pragma unroll
            for (int h = 0; h < HH; h++)
                t[h] += __shfl_xor_sync(0xffffffffu, t[h], off);
        if (lane == 0) {
            float4 o0 = make_float4(t[0], t[1], t[2], t[3]);
            float4 o1 = make_float4(t[4], t[5], t[6], t[7]);
            ((float4*)g_u)[n0 * 2]        = o0;
            ((float4*)g_u)[n0 * 2 + 1]    = o1;
            ((float4*)g_agg1)[n0 * 2]     = o0;   // raw self seed (corrected in D)
            ((float4*)g_agg1)[n0 * 2 + 1] = o1;
        } else if (lane == 16 && has1) {
            float4 o0 = make_float4(t[0], t[1], t[2], t[3]);
            float4 o1 = make_float4(t[4], t[5], t[6], t[7]);
            ((float4*)g_u)[n1 * 2]        = o0;
            ((float4*)g_u)[n1 * 2 + 1]    = o1;
            ((float4*)g_agg1)[n1 * 2]     = o0;
            ((float4*)g_agg1)[n1 * 2 + 1] = o1;
        }
    }
    gsync(base + 1, nb);

    // ===== Phase C: scatter agg1 += u_raw[src]*dinv[src]; 2 edges/thread ======
    for (int i = gtid; 2 * i < E; i += T) {
        int e0 = 2 * i;
        bool h1 = (e0 + 1 < E);
        int4 p = *(const int4*)&g_edge[e0];   // (src0,dst0,src1,dst1)
        int s1i = h1 ? p.z : p.x;
        float ds0 = rsqrtf(1.0f + (float)__ldg(&g_degi[p.x]));
        float ds1 = rsqrtf(1.0f + (float)__ldg(&g_degi[s1i]));
        float4 a0 = __ldg((const float4*)(g_u + (size_t)p.x * HH));
        float4 b0 = __ldg((const float4*)(g_u + (size_t)p.x * HH) + 1);
        float4 a1 = __ldg((const float4*)(g_u + (size_t)s1i * HH));
        float4 b1_ = __ldg((const float4*)(g_u + (size_t)s1i * HH) + 1);
        a0.x *= ds0; a0.y *= ds0; a0.z *= ds0; a0.w *= ds0;
        b0.x *= ds0; b0.y *= ds0; b0.z *= ds0; b0.w *= ds0;
        red_add_v4(g_agg1 + (size_t)p.y * HH,     a0);
        red_add_v4(g_agg1 + (size_t)p.y * HH + 4, b0);
        if (h1) {
            a1.x *= ds1; a1.y *= ds1; a1.z *= ds1; a1.w *= ds1;
            b1_.x *= ds1; b1_.y *= ds1; b1_.z *= ds1; b1_.w *= ds1;
            red_add_v4(g_agg1 + (size_t)p.w * HH,     a1);
            red_add_v4(g_agg1 + (size_t)p.w * HH + 4, b1_);
        }
    }
    gsync(base + 2, nb);

    // ====== Phase D: seed-fix + bias + LN + ReLU + dinv; seed agg2 ============
    {
        float B1[HH], G[HH], BT[HH];
#pragma unroll
        for (int k = 0; k < HH; k++) {
            B1[k] = __ldg(&b1[k]); G[k] = __ldg(&gamma[k]); BT[k] = __ldg(&beta[k]);
        }
        for (int n = gtid; n < N; n += T) {
            float di = rsqrtf(1.0f + (float)g_degi[n]);
            float4 p0 = ((const float4*)g_agg1)[n * 2];
            float4 p1 = ((const float4*)g_agg1)[n * 2 + 1];
            float4 q0 = ((const float4*)g_u)[n * 2];
            float4 q1 = ((const float4*)g_u)[n * 2 + 1];
            float h[HH] = {p0.x, p0.y, p0.z, p0.w, p1.x, p1.y, p1.z, p1.w};
            float q[HH] = {q0.x, q0.y, q0.z, q0.w, q1.x, q1.y, q1.z, q1.w};
            float dm1 = di - 1.0f;
            float mu = 0.f;
#pragma unroll
            for (int k = 0; k < HH; k++) {
                // agg1 held u_raw[n] as seed; correct to u_raw[n]*di, then *di+b1
                h[k] = fmaf(q[k], dm1, h[k]) * di + B1[k];
                mu += h[k];
            }
            mu *= 0.125f;
            float var = 0.f;
#pragma unroll
            for (int k = 0; k < HH; k++) { float d = h[k] - mu; var += d * d; }
            var *= 0.125f;
            float r = rsqrtf(var + LN_EPS);
            float v[HH];
#pragma unroll
            for (int k = 0; k < HH; k++) {
                float hn = (h[k] - mu) * r * G[k] + BT[k];
                v[k] = fmaxf(hn, 0.f) * di;
            }
            float4 o0 = make_float4(v[0], v[1], v[2], v[3]);
            float4 o1 = make_float4(v[4], v[5], v[6], v[7]);
            ((float4*)g_v)[n * 2]        = o0;
            ((float4*)g_v)[n * 2 + 1]    = o1;
            ((float4*)g_agg2)[n * 2]     = o0;   // self-loop seed (v fully scaled)
            ((float4*)g_agg2)[n * 2 + 1] = o1;
        }
    }
    gsync(base + 3, nb);

    // ================= Phase E: scatter agg2 += v[src]; 2 edges/thread ========
    for (int i = gtid; 2 * i < E; i += T) {
        int e0 = 2 * i;
        bool h1 = (e0 + 1 < E);
        int4 p = *(const int4*)&g_edge[e0];
        int s1i = h1 ? p.z : p.x;
        float4 a0 = __ldg((const float4*)(g_v + (size_t)p.x * HH));
        float4 b0 = __ldg((const float4*)(g_v + (size_t)p.x * HH) + 1);
        float4 a1 = __ldg((const float4*)(g_v + (size_t)s1i * HH));
        float4 b1_ = __ldg((const float4*)(g_v + (size_t)s1i * HH) + 1);
        red_add_v4(g_agg2 + (size_t)p.y * HH,     a0);
        red_add_v4(g_agg2 + (size_t)p.y * HH + 4, b0);
        if (h1) {
            red_add_v4(g_agg2 + (size_t)p.w * HH,     a1);
            red_add_v4(g_agg2 + (size_t)p.w * HH + 4, b1_);
        }
    }
    gsync(base + 4, nb);

    // ================= Phase F: GEMM2 + relu + sf; warp per 4 nodes, f32x2 ====
    for (int i = tid; i < DD * HH; i += TPB) s_w[i] = W2[i];
    for (int i = tid; i < DD; i += TPB)      s_w[DD * HH + i] = b2[i];
    __syncthreads();

    for (int n0 = gwarp * 4; n0 < N; n0 += W * 4) {
        int nl = n0 + (lane >> 3); if (nl >= N) nl = N - 1;
        float di  = rsqrtf(1.0f + (float)g_degi[nl]);
        float myv = g_agg2[(size_t)nl * HH + (lane & 7)] * di;
        float sfv = sf[nl];
        float a[4][HH];
        float s[4];
#pragma unroll
        for (int i = 0; i < 4; i++) {
            s[i] = __shfl_sync(0xffffffffu, sfv, i * 8);
#pragma unroll
            for (int h = 0; h < HH; h++)
                a[i][h] = __shfl_sync(0xffffffffu, myv, i * 8 + h);
        }
#pragma unroll
        for (int j = 0; j < 4; j++) {
            int d4 = lane + 32 * j;
            ulonglong2 bias = ((const ulonglong2*)&s_w[DD * HH])[d4];
            ulonglong2 A0 = bias, A1 = bias, A2 = bias, A3 = bias;
#pragma unroll
            for (int h = 0; h < HH; h++) {
                ulonglong2 w = ((const ulonglong2*)s_w)[h * (DD / 4) + d4]; // LDS.128
                u64 p0 = fpack2(a[0][h]);
                u64 p1 = fpack2(a[1][h]);
                u64 p2 = fpack2(a[2][h]);
                u64 p3 = fpack2(a[3][h]);
                A0.x = ffma2(p0, w.x, A0.x);  A0.y = ffma2(p0, w.y, A0.y);
                A1.x = ffma2(p1, w.x, A1.x);  A1.y = ffma2(p1, w.y, A1.y);
                A2.x = ffma2(p2, w.x, A2.x);  A2.y = ffma2(p2, w.y, A2.y);
                A3.x = ffma2(p3, w.x, A3.x);  A3.y = ffma2(p3, w.y, A3.y);
            }
            float2 l0 = funpack2(A0.x), h0 = funpack2(A0.y);
            float2 l1 = funpack2(A1.x), h1 = funpack2(A1.y);
            float2 l2 = funpack2(A2.x), h2 = funpack2(A2.y);
            float2 l3 = funpack2(A3.x), h3 = funpack2(A3.y);
            float4 r0 = make_float4(fmaxf(l0.x,0.f)*s[0], fmaxf(l0.y,0.f)*s[0],
                                    fmaxf(h0.x,0.f)*s[0], fmaxf(h0.y,0.f)*s[0]);
            float4 r1 = make_float4(fmaxf(l1.x,0.f)*s[1], fmaxf(l1.y,0.f)*s[1],
                                    fmaxf(h1.x,0.f)*s[1], fmaxf(h1.y,0.f)*s[1]);
            float4 r2 = make_float4(fmaxf(l2.x,0.f)*s[2], fmaxf(l2.y,0.f)*s[2],
                                    fmaxf(h2.x,0.f)*s[2], fmaxf(h2.y,0.f)*s[2]);
            float4 r3 = make_float4(fmaxf(l3.x,0.f)*s[3], fmaxf(l3.y,0.f)*s[3],
                                    fmaxf(h3.x,0.f)*s[3], fmaxf(h3.y,0.f)*s[3]);
            if (n0 + 0 < N) __stcs((float4*)out + (size_t)(n0+0) * (DD/4) + d4, r0);
            if (n0 + 1 < N) __stcs((float4*)out + (size_t)(n0+1) * (DD/4) + d4, r1);
            if (n0 + 2 < N) __stcs((float4*)out + (size_t)(n0+2) * (DD/4) + d4, r2);
            if (n0 + 3 < N) __stcs((float4*)out + (size_t)(n0+3) * (DD/4) + d4, r3);
        }
        if (lane < 4 && n0 + lane < N) g_degi[n0 + lane] = 0;  // restore invariant
    }
}

// ---------------- launch -------------------------------------------------------
extern "C" void kernel_launch(void* const* d_in, const int* in_sizes, int n_in,
                              void* d_out, int out_size) {
    const float* x     = (const float*)d_in[0];
    const float* sf    = (const float*)d_in[1];
    const float* W1    = (const float*)d_in[2];
    const float* b1    = (const float*)d_in[3];
    const float* gamma = (const float*)d_in[4];
    const float* beta  = (const float*)d_in[5];
    const float* W2    = (const float*)d_in[6];
    const float* b2    = (const float*)d_in[7];
    const int*   ei    = (const int*)d_in[8];
    float* out = (float*)d_out;

    int N = in_sizes[0] / DD;
    int E = in_sizes[8] / 2;
    if (N > MAXN) N = MAXN;
    if (E > MAXE) E = MAXE;

    static int s_grid = 0;
    if (s_grid == 0) {
        int nsm = 0, bps = 0;
        cudaDeviceGetAttribute(&nsm, cudaDevAttrMultiProcessorCount, 0);
        cudaOccupancyMaxActiveBlocksPerMultiprocessor(&bps, k_fused, TPB, 0);
        if (nsm <= 0) nsm = 148;
        if (bps <= 0) bps = 2;
        s_grid = nsm * bps;
        if (s_grid > MAXB) s_grid = MAXB;
    }
    unsigned nb = (unsigned)s_grid;
    k_fused<<<s_grid, TPB>>>(x, sf, W1, b1, gamma, beta, W2, b2, ei, out,
                             N, E, nb);
}

// round 14
// speedup vs baseline: 1.0438x; 1.0438x over previous
#include <cuda_runtime.h>
#include <stdint.h>

#define DD 512
#define HH 8
#define MAXN 50048
#define MAXE 800000
#define LN_EPS 1e-5f
#define TPB 256

typedef unsigned long long u64;

// ---------------- scratch (device globals; zero-initialized at load) -----------
__device__ __align__(16) int   g_degi[MAXN];     // invariant: zero at call entry
__device__ __align__(16) float g_u   [MAXN * HH];   // raw x@W1
__device__ __align__(16) float g_agg1[MAXN * HH];
__device__ __align__(16) float g_v   [MAXN * HH];
__device__ __align__(16) float g_agg2[MAXN * HH];
__device__ __align__(16) int2  g_edge[MAXE];
__device__ unsigned g_bar;                        // monotonic, never reset

// ---------------- helpers ------------------------------------------------------
__device__ __forceinline__ void red_add_v4(float* addr, float4 v) {
    asm volatile("red.global.add.v4.f32 [%0], {%1,%2,%3,%4};"
                 :: "l"(addr), "f"(v.x), "f"(v.y), "f"(v.z), "f"(v.w)
                 : "memory");
}

// packed f32x2 FMA: d = a*b + c on both 32-bit halves (1 issue slot, 2 FMAs)
__device__ __forceinline__ u64 ffma2(u64 a, u64 b, u64 c) {
    u64 d;
    asm("fma.rn.f32x2 %0, %1, %2, %3;" : "=l"(d) : "l"(a), "l"(b), "l"(c));
    return d;
}
__device__ __forceinline__ u64 fpack2(float v) {          // (v, v)
    u64 d; asm("mov.b64 %0, {%1, %1};" : "=l"(d) : "f"(v)); return d;
}
__device__ __forceinline__ float2 funpack2(u64 v) {
    float2 r; asm("mov.b64 {%0, %1}, %2;" : "=f"(r.x), "=f"(r.y) : "l"(v));
    return r;
}

// Monotonic grid barrier: safe across graph replays (no reset needed).
__device__ __forceinline__ void gsync(unsigned nb) {
    __syncthreads();
    if (threadIdx.x == 0) {
        __threadfence();
        unsigned my = atomicAdd(&g_bar, 1u);
        unsigned target = my - (my % nb) + nb;
        while ((int)(*(volatile unsigned*)&g_bar - target) < 0) __nanosleep(64);
        __threadfence();
    }
    __syncthreads();
}

// ---------------- the single persistent kernel ---------------------------------
__global__ void __launch_bounds__(TPB, 4)
k_fused(const float* __restrict__ x,
        const float* __restrict__ sf,
        const float* __restrict__ W1,
        const float* __restrict__ b1,
        const float* __restrict__ gamma,
        const float* __restrict__ beta,
        const float* __restrict__ W2,
        const float* __restrict__ b2,
        const int*   __restrict__ ei,
        float* __restrict__ out,
        int N, int E, unsigned nb) {
    const int tid   = threadIdx.x;
    const int gtid  = blockIdx.x * TPB + tid;
    const int T     = gridDim.x * TPB;
    const int lane  = tid & 31;
    const int gwarp = gtid >> 5;
    const int W     = T >> 5;

    // s_w1: W1 transposed (16 KB).  s_w2: W2 | b2 (18 KB) — staged in prologue
    // so phase F starts immediately after the last grid barrier.
    __shared__ float s_w1[DD * HH];
    __shared__ float s_w2[DD * HH + DD];
    __shared__ int   s_is64;

    // ---- prologue: stage W1 (transposed) + W2|b2 + int64/int32 detection ----
    for (int i = tid; i < DD * HH; i += TPB) {
        int c = i >> 3, h = i & 7;           // W1 is [DD][HH] row-major
        s_w1[h * DD + c] = W1[i];
        s_w2[i] = W2[i];
    }
    for (int i = tid; i < DD; i += TPB) s_w2[DD * HH + i] = b2[i];
    if (tid == 0) {
        int f = 1;
        int lim = 2 * E < 32 ? 2 * E : 32;
        for (int w = 1; w < lim; w += 2)
            if (ei[w] != 0) { f = 0; break; }
        s_is64 = f;
    }
    __syncthreads();

    // ================= Phase A: edge prep + raw GEMM1 (independent) ==========
    {
        const int is64 = s_is64;
        for (int e = gtid; e < E; e += T) {
            int src, dst;
            if (is64) {
                src = ((const int2*)ei)[e].x;
                dst = ((const int2*)ei)[(size_t)E + e].x;
            } else {
                src = ei[e];
                dst = ei[E + e];
            }
            g_edge[e] = make_int2(src, dst);
            atomicAdd(&g_degi[dst], 1);
        }
    }
    // raw u = x @ W1; warp per 2 nodes; prefetched LDG.128, f32x2 FMAs
    for (int n0 = gwarp * 2; n0 < N; n0 += W * 2) {
        const int  n1   = n0 + 1;
        const bool has1 = (n1 < N);
        const ulonglong2* x0 = (const ulonglong2*)(x + (size_t)n0 * DD);
        const ulonglong2* x1 = (const ulonglong2*)(x + (size_t)(has1 ? n1 : n0) * DD);
        u64 acc0[HH], acc1[HH];
#pragma unroll
        for (int h = 0; h < HH; h++) { acc0[h] = 0ull; acc1[h] = 0ull; }

        ulonglong2 pa = __ldcs(&x0[lane]);
        ulonglong2 pb = __ldcs(&x1[lane]);
#pragma unroll
        for (int it = 0; it < 4; it++) {
            ulonglong2 xv0 = pa, xv1 = pb;
            if (it < 3) {                       // prefetch next tile
                pa = __ldcs(&x0[lane + (it + 1) * 32]);
                pb = __ldcs(&x1[lane + (it + 1) * 32]);
            }
            int c4 = lane + it * 32;
#pragma unroll
            for (int h = 0; h < HH; h++) {
                ulonglong2 w = *((const ulonglong2*)(s_w1 + h * DD) + c4); // LDS.128
                acc0[h] = ffma2(xv0.x, w.x, acc0[h]);
                acc0[h] = ffma2(xv0.y, w.y, acc0[h]);
                acc1[h] = ffma2(xv1.x, w.x, acc1[h]);
                acc1[h] = ffma2(xv1.y, w.y, acc1[h]);
            }
        }
        // horizontal: pair-sum, 1 full butterfly, split nodes across half-warps
        float t[HH];
#pragma unroll
        for (int h = 0; h < HH; h++) {
            float2 p0 = funpack2(acc0[h]);
            float2 p1 = funpack2(acc1[h]);
            float s0 = p0.x + p0.y, s1 = p1.x + p1.y;
            s0 += __shfl_xor_sync(0xffffffffu, s0, 16);
            s1 += __shfl_xor_sync(0xffffffffu, s1, 16);
            t[h] = (lane & 16) ? s1 : s0;
        }
#pragma unroll
        for (int off = 8; off; off >>= 1)
#pragma unroll
            for (int h = 0; h < HH; h++)
                t[h] += __shfl_xor_sync(0xffffffffu, t[h], off);
        if (lane == 0) {
            float4 o0 = make_float4(t[0], t[1], t[2], t[3]);
            float4 o1 = make_float4(t[4], t[5], t[6], t[7]);
            ((float4*)g_u)[n0 * 2]        = o0;
            ((float4*)g_u)[n0 * 2 + 1]    = o1;
            ((float4*)g_agg1)[n0 * 2]     = o0;   // raw self seed (corrected in D)
            ((float4*)g_agg1)[n0 * 2 + 1] = o1;
        } else if (lane == 16 && has1) {
            float4 o0 = make_float4(t[0], t[1], t[2], t[3]);
            float4 o1 = make_float4(t[4], t[5], t[6], t[7]);
            ((float4*)g_u)[n1 * 2]        = o0;
            ((float4*)g_u)[n1 * 2 + 1]    = o1;
            ((float4*)g_agg1)[n1 * 2]     = o0;
            ((float4*)g_agg1)[n1 * 2 + 1] = o1;
        }
    }
    gsync(nb);

    // ===== Phase C: scatter agg1 += u_raw[src]*dinv[src]; 2 edges/thread ======
    for (int i = gtid; 2 * i < E; i += T) {
        int e0 = 2 * i;
        bool h1 = (e0 + 1 < E);
        int4 p = *(const int4*)&g_edge[e0];   // (src0,dst0,src1,dst1)
        int s1i = h1 ? p.z : p.x;
        float ds0 = rsqrtf(1.0f + (float)__ldg(&g_degi[p.x]));
        float ds1 = rsqrtf(1.0f + (float)__ldg(&g_degi[s1i]));
        float4 a0 = __ldg((const float4*)(g_u + (size_t)p.x * HH));
        float4 b0 = __ldg((const float4*)(g_u + (size_t)p.x * HH) + 1);
        float4 a1 = __ldg((const float4*)(g_u + (size_t)s1i * HH));
        float4 b1_ = __ldg((const float4*)(g_u + (size_t)s1i * HH) + 1);
        a0.x *= ds0; a0.y *= ds0; a0.z *= ds0; a0.w *= ds0;
        b0.x *= ds0; b0.y *= ds0; b0.z *= ds0; b0.w *= ds0;
        red_add_v4(g_agg1 + (size_t)p.y * HH,     a0);
        red_add_v4(g_agg1 + (size_t)p.y * HH + 4, b0);
        if (h1) {
            a1.x *= ds1; a1.y *= ds1; a1.z *= ds1; a1.w *= ds1;
            b1_.x *= ds1; b1_.y *= ds1; b1_.z *= ds1; b1_.w *= ds1;
            red_add_v4(g_agg1 + (size_t)p.w * HH,     a1);
            red_add_v4(g_agg1 + (size_t)p.w * HH + 4, b1_);
        }
    }
    gsync(nb);

    // ====== Phase D: seed-fix + bias + LN + ReLU + dinv; seed agg2 ============
    {
        float B1[HH], G[HH], BT[HH];
#pragma unroll
        for (int k = 0; k < HH; k++) {
            B1[k] = __ldg(&b1[k]); G[k] = __ldg(&gamma[k]); BT[k] = __ldg(&beta[k]);
        }
        for (int n = gtid; n < N; n += T) {
            float di = rsqrtf(1.0f + (float)g_degi[n]);
            float4 p0 = ((const float4*)g_agg1)[n * 2];
            float4 p1 = ((const float4*)g_agg1)[n * 2 + 1];
            float4 q0 = ((const float4*)g_u)[n * 2];
            float4 q1 = ((const float4*)g_u)[n * 2 + 1];
            float h[HH] = {p0.x, p0.y, p0.z, p0.w, p1.x, p1.y, p1.z, p1.w};
            float q[HH] = {q0.x, q0.y, q0.z, q0.w, q1.x, q1.y, q1.z, q1.w};
            float dm1 = di - 1.0f;
            float mu = 0.f;
#pragma unroll
            for (int k = 0; k < HH; k++) {
                // agg1 held u_raw[n] as seed; correct to u_raw[n]*di, then *di+b1
                h[k] = fmaf(q[k], dm1, h[k]) * di + B1[k];
                mu += h[k];
            }
            mu *= 0.125f;
            float var = 0.f;
#pragma unroll
            for (int k = 0; k < HH; k++) { float d = h[k] - mu; var += d * d; }
            var *= 0.125f;
            float r = rsqrtf(var + LN_EPS);
            float v[HH];
#pragma unroll
            for (int k = 0; k < HH; k++) {
                float hn = (h[k] - mu) * r * G[k] + BT[k];
                v[k] = fmaxf(hn, 0.f) * di;
            }
            float4 o0 = make_float4(v[0], v[1], v[2], v[3]);
            float4 o1 = make_float4(v[4], v[5], v[6], v[7]);
            ((float4*)g_v)[n * 2]        = o0;
            ((float4*)g_v)[n * 2 + 1]    = o1;
            ((float4*)g_agg2)[n * 2]     = o0;   // self-loop seed (v fully scaled)
            ((float4*)g_agg2)[n * 2 + 1] = o1;
        }
    }
    gsync(nb);

    // ================= Phase E: scatter agg2 += v[src]; 2 edges/thread ========
    for (int i = gtid; 2 * i < E; i += T) {
        int e0 = 2 * i;
        bool h1 = (e0 + 1 < E);
        int4 p = *(const int4*)&g_edge[e0];
        int s1i = h1 ? p.z : p.x;
        float4 a0 = __ldg((const float4*)(g_v + (size_t)p.x * HH));
        float4 b0 = __ldg((const float4*)(g_v + (size_t)p.x * HH) + 1);
        float4 a1 = __ldg((const float4*)(g_v + (size_t)s1i * HH));
        float4 b1_ = __ldg((const float4*)(g_v + (size_t)s1i * HH) + 1);
        red_add_v4(g_agg2 + (size_t)p.y * HH,     a0);
        red_add_v4(g_agg2 + (size_t)p.y * HH + 4, b0);
        if (h1) {
            red_add_v4(g_agg2 + (size_t)p.w * HH,     a1);
            red_add_v4(g_agg2 + (size_t)p.w * HH + 4, b1_);
        }
    }
    gsync(nb);

    // ============ Phase F: GEMM2 + relu + sf (weights pre-staged) =============
    for (int n0 = gwarp * 4; n0 < N; n0 += W * 4) {
        int nl = n0 + (lane >> 3); if (nl >= N) nl = N - 1;
        float di  = rsqrtf(1.0f + (float)g_degi[nl]);
        float myv = g_agg2[(size_t)nl * HH + (lane & 7)] * di;
        float sfv = sf[nl];
        float a[4][HH];
        float s[4];
#pragma unroll
        for (int i = 0; i < 4; i++) {
            s[i] = __shfl_sync(0xffffffffu, sfv, i * 8);
#pragma unroll
            for (int h = 0; h < HH; h++)
                a[i][h] = __shfl_sync(0xffffffffu, myv, i * 8 + h);
        }
#pragma unroll
        for (int j = 0; j < 4; j++) {
            int d4 = lane + 32 * j;
            ulonglong2 bias = ((const ulonglong2*)&s_w2[DD * HH])[d4];
            ulonglong2 A0 = bias, A1 = bias, A2 = bias, A3 = bias;
#pragma unroll
            for (int h = 0; h < HH; h++) {
                ulonglong2 w = ((const ulonglong2*)s_w2)[h * (DD / 4) + d4]; // LDS.128
                u64 p0 = fpack2(a[0][h]);
                u64 p1 = fpack2(a[1][h]);
                u64 p2 = fpack2(a[2][h]);
                u64 p3 = fpack2(a[3][h]);
                A0.x = ffma2(p0, w.x, A0.x);  A0.y = ffma2(p0, w.y, A0.y);
                A1.x = ffma2(p1, w.x, A1.x);  A1.y = ffma2(p1, w.y, A1.y);
                A2.x = ffma2(p2, w.x, A2.x);  A2.y = ffma2(p2, w.y, A2.y);
                A3.x = ffma2(p3, w.x, A3.x);  A3.y = ffma2(p3, w.y, A3.y);
            }
            float2 l0 = funpack2(A0.x), h0 = funpack2(A0.y);
            float2 l1 = funpack2(A1.x), h1 = funpack2(A1.y);
            float2 l2 = funpack2(A2.x), h2 = funpack2(A2.y);
            float2 l3 = funpack2(A3.x), h3 = funpack2(A3.y);
            float4 r0 = make_float4(fmaxf(l0.x,0.f)*s[0], fmaxf(l0.y,0.f)*s[0],
                                    fmaxf(h0.x,0.f)*s[0], fmaxf(h0.y,0.f)*s[0]);
            float4 r1 = make_float4(fmaxf(l1.x,0.f)*s[1], fmaxf(l1.y,0.f)*s[1],
                                    fmaxf(h1.x,0.f)*s[1], fmaxf(h1.y,0.f)*s[1]);
            float4 r2 = make_float4(fmaxf(l2.x,0.f)*s[2], fmaxf(l2.y,0.f)*s[2],
                                    fmaxf(h2.x,0.f)*s[2], fmaxf(h2.y,0.f)*s[2]);
            float4 r3 = make_float4(fmaxf(l3.x,0.f)*s[3], fmaxf(l3.y,0.f)*s[3],
                                    fmaxf(h3.x,0.f)*s[3], fmaxf(h3.y,0.f)*s[3]);
            if (n0 + 0 < N) __stcs((float4*)out + (size_t)(n0+0) * (DD/4) + d4, r0);
            if (n0 + 1 < N) __stcs((float4*)out + (size_t)(n0+1) * (DD/4) + d4, r1);
            if (n0 + 2 < N) __stcs((float4*)out + (size_t)(n0+2) * (DD/4) + d4, r2);
            if (n0 + 3 < N) __stcs((float4*)out + (size_t)(n0+3) * (DD/4) + d4, r3);
        }
        if (lane < 4 && n0 + lane < N) g_degi[n0 + lane] = 0;  // restore invariant
    }
}

// ---------------- launch -------------------------------------------------------
extern "C" void kernel_launch(void* const* d_in, const int* in_sizes, int n_in,
                              void* d_out, int out_size) {
    const float* x     = (const float*)d_in[0];
    const float* sf    = (const float*)d_in[1];
    const float* W1    = (const float*)d_in[2];
    const float* b1    = (const float*)d_in[3];
    const float* gamma = (const float*)d_in[4];
    const float* beta  = (const float*)d_in[5];
    const float* W2    = (const float*)d_in[6];
    const float* b2    = (const float*)d_in[7];
    const int*   ei    = (const int*)d_in[8];
    float* out = (float*)d_out;

    int N = in_sizes[0] / DD;
    int E = in_sizes[8] / 2;
    if (N > MAXN) N = MAXN;
    if (E > MAXE) E = MAXE;

    static int s_grid = 0;
    if (s_grid == 0) {
        int nsm = 0, bps = 0;
        cudaDeviceGetAttribute(&nsm, cudaDevAttrMultiProcessorCount, 0);
        cudaOccupancyMaxActiveBlocksPerMultiprocessor(&bps, k_fused, TPB, 0);
        if (nsm <= 0) nsm = 148;
        if (bps <= 0) bps = 2;
        s_grid = nsm * bps;
    }
    unsigned nb = (unsigned)s_grid;
    k_fused<<<s_grid, TPB>>>(x, sf, W1, b1, gamma, beta, W2, b2, ei, out,
                             N, E, nb);
}

// round 15
// speedup vs baseline: 1.0619x; 1.0174x over previous
#include <cuda_runtime.h>
#include <stdint.h>

#define DD 512
#define HH 8
#define MAXN 50048
#define MAXE 800000
#define LN_EPS 1e-5f
#define TPB 256

typedef unsigned long long u64;

// ---------------- scratch (device globals; zero-initialized at load) -----------
__device__ __align__(16) int   g_degi[MAXN];     // invariant: zero at call entry
__device__ __align__(16) float g_u   [MAXN * HH];   // raw x@W1
__device__ __align__(16) float g_agg1[MAXN * HH];   // invariant: zero at call entry
__device__ __align__(16) float g_v   [MAXN * HH];
__device__ __align__(16) float g_agg2[MAXN * HH];
__device__ __align__(16) int2  g_edge[MAXE];
__device__ unsigned g_bar;                        // monotonic, never reset

// ---------------- helpers ------------------------------------------------------
__device__ __forceinline__ void red_add_v4(float* addr, float4 v) {
    asm volatile("red.global.add.v4.f32 [%0], {%1,%2,%3,%4};"
                 :: "l"(addr), "f"(v.x), "f"(v.y), "f"(v.z), "f"(v.w)
                 : "memory");
}

// packed f32x2 ops (sm_103a): 1 issue slot, 2 float lanes
__device__ __forceinline__ u64 ffma2(u64 a, u64 b, u64 c) {
    u64 d;
    asm("fma.rn.f32x2 %0, %1, %2, %3;" : "=l"(d) : "l"(a), "l"(b), "l"(c));
    return d;
}
__device__ __forceinline__ u64 fmul2(u64 a, u64 b) {
    u64 d;
    asm("mul.rn.f32x2 %0, %1, %2;" : "=l"(d) : "l"(a), "l"(b));
    return d;
}
__device__ __forceinline__ u64 fpack2(float v) {          // (v, v)
    u64 d; asm("mov.b64 %0, {%1, %1};" : "=l"(d) : "f"(v)); return d;
}
__device__ __forceinline__ float2 funpack2(u64 v) {
    float2 r; asm("mov.b64 {%0, %1}, %2;" : "=f"(r.x), "=f"(r.y) : "l"(v));
    return r;
}
__device__ __forceinline__ void red_add_v4u(float* addr, ulonglong2 v) {
    float2 a = funpack2(v.x), b = funpack2(v.y);
    red_add_v4(addr, make_float4(a.x, a.y, b.x, b.y));
}

// Monotonic grid barrier: safe across graph replays (no reset needed).
__device__ __forceinline__ void gsync(unsigned nb) {
    __syncthreads();
    if (threadIdx.x == 0) {
        __threadfence();
        unsigned my = atomicAdd(&g_bar, 1u);
        unsigned target = my - (my % nb) + nb;
        while ((int)(*(volatile unsigned*)&g_bar - target) < 0) __nanosleep(32);
        __threadfence();
    }
    __syncthreads();
}

// ---------------- the single persistent kernel ---------------------------------
__global__ void __launch_bounds__(TPB, 4)
k_fused(const float* __restrict__ x,
        const float* __restrict__ sf,
        const float* __restrict__ W1,
        const float* __restrict__ b1,
        const float* __restrict__ gamma,
        const float* __restrict__ beta,
        const float* __restrict__ W2,
        const float* __restrict__ b2,
        const int*   __restrict__ ei,
        float* __restrict__ out,
        int N, int E, unsigned nb) {
    const int tid   = threadIdx.x;
    const int gtid  = blockIdx.x * TPB + tid;
    const int T     = gridDim.x * TPB;
    const int lane  = tid & 31;
    const int gwarp = gtid >> 5;
    const int W     = T >> 5;

    // s_w1: W1 transposed (16 KB).  s_w2: W2 | b2 (18 KB), staged in prologue.
    __shared__ float s_w1[DD * HH];
    __shared__ float s_w2[DD * HH + DD];
    __shared__ int   s_is64;

    // ---- prologue: stage W1 (transposed) + W2|b2 + int64/int32 detection ----
    for (int i = tid; i < DD * HH; i += TPB) {
        int c = i >> 3, h = i & 7;           // W1 is [DD][HH] row-major
        s_w1[h * DD + c] = W1[i];
        s_w2[i] = W2[i];
    }
    for (int i = tid; i < DD; i += TPB) s_w2[DD * HH + i] = b2[i];
    if (tid == 0) {
        int f = 1;
        int lim = 2 * E < 32 ? 2 * E : 32;
        for (int w = 1; w < lim; w += 2)
            if (ei[w] != 0) { f = 0; break; }
        s_is64 = f;
    }
    __syncthreads();

    // ================= Phase A: edge prep + raw GEMM1 (independent) ==========
    {
        const int is64 = s_is64;
        if ((E & 1) == 0) {
            // vectorized: 2 edges per thread, wide loads + one int4 store
            for (int i = gtid; 2 * i < E; i += T) {
                int s0, d0, s1, d1;
                if (is64) {
                    int4 sv = ((const int4*)ei)[i];           // int64 pair (lo,hi)x2
                    int4 dv = ((const int4*)ei)[(E >> 1) + i];
                    s0 = sv.x; s1 = sv.z; d0 = dv.x; d1 = dv.z;
                } else {
                    int2 sv = ((const int2*)ei)[i];
                    int2 dv = *(const int2*)(ei + E + 2 * i);
                    s0 = sv.x; s1 = sv.y; d0 = dv.x; d1 = dv.y;
                }
                *(int4*)&g_edge[2 * i] = make_int4(s0, d0, s1, d1);
                atomicAdd(&g_degi[d0], 1);
                atomicAdd(&g_degi[d1], 1);
            }
        } else {
            for (int e = gtid; e < E; e += T) {
                int src, dst;
                if (is64) {
                    src = ((const int2*)ei)[e].x;
                    dst = ((const int2*)ei)[(size_t)E + e].x;
                } else {
                    src = ei[e];
                    dst = ei[E + e];
                }
                g_edge[e] = make_int2(src, dst);
                atomicAdd(&g_degi[dst], 1);
            }
        }
    }
    // raw u = x @ W1; warp per 2 nodes; prefetched LDG.128, f32x2 FMAs
    for (int n0 = gwarp * 2; n0 < N; n0 += W * 2) {
        const int  n1   = n0 + 1;
        const bool has1 = (n1 < N);
        const ulonglong2* x0 = (const ulonglong2*)(x + (size_t)n0 * DD);
        const ulonglong2* x1 = (const ulonglong2*)(x + (size_t)(has1 ? n1 : n0) * DD);
        u64 acc0[HH], acc1[HH];
#pragma unroll
        for (int h = 0; h < HH; h++) { acc0[h] = 0ull; acc1[h] = 0ull; }

        ulonglong2 pa = __ldcs(&x0[lane]);
        ulonglong2 pb = __ldcs(&x1[lane]);
#pragma unroll
        for (int it = 0; it < 4; it++) {
            ulonglong2 xv0 = pa, xv1 = pb;
            if (it < 3) {                       // prefetch next tile
                pa = __ldcs(&x0[lane + (it + 1) * 32]);
                pb = __ldcs(&x1[lane + (it + 1) * 32]);
            }
            int c4 = lane + it * 32;
#pragma unroll
            for (int h = 0; h < HH; h++) {
                ulonglong2 w = *((const ulonglong2*)(s_w1 + h * DD) + c4); // LDS.128
                acc0[h] = ffma2(xv0.x, w.x, acc0[h]);
                acc0[h] = ffma2(xv0.y, w.y, acc0[h]);
                acc1[h] = ffma2(xv1.x, w.x, acc1[h]);
                acc1[h] = ffma2(xv1.y, w.y, acc1[h]);
            }
        }
        // horizontal: pair-sum, 1 full butterfly, split nodes across half-warps
        float t[HH];
#pragma unroll
        for (int h = 0; h < HH; h++) {
            float2 p0 = funpack2(acc0[h]);
            float2 p1 = funpack2(acc1[h]);
            float s0 = p0.x + p0.y, s1 = p1.x + p1.y;
            s0 += __shfl_xor_sync(0xffffffffu, s0, 16);
            s1 += __shfl_xor_sync(0xffffffffu, s1, 16);
            t[h] = (lane & 16) ? s1 : s0;
        }
#pragma unroll
        for (int off = 8; off; off >>= 1)
#pragma unroll
            for (int h = 0; h < HH; h++)
                t[h] += __shfl_xor_sync(0xffffffffu, t[h], off);
        if (lane == 0) {
            ((float4*)g_u)[n0 * 2]     = make_float4(t[0], t[1], t[2], t[3]);
            ((float4*)g_u)[n0 * 2 + 1] = make_float4(t[4], t[5], t[6], t[7]);
        } else if (lane == 16 && has1) {
            ((float4*)g_u)[n1 * 2]     = make_float4(t[0], t[1], t[2], t[3]);
            ((float4*)g_u)[n1 * 2 + 1] = make_float4(t[4], t[5], t[6], t[7]);
        }
    }
    gsync(nb);

    // ===== Phase C: scatter agg1 += u_raw[src]*dinv[src]; 2 edges/thread ======
    // (agg1 is zero at entry; self-loop term added analytically in phase D)
    for (int i = gtid; 2 * i < E; i += T) {
        int e0 = 2 * i;
        bool h1 = (e0 + 1 < E);
        int4 p = *(const int4*)&g_edge[e0];   // (src0,dst0,src1,dst1)
        int s1i = h1 ? p.z : p.x;
        float ds0 = rsqrtf(1.0f + (float)__ldg(&g_degi[p.x]));
        float ds1 = rsqrtf(1.0f + (float)__ldg(&g_degi[s1i]));
        ulonglong2 A0 = __ldg((const ulonglong2*)(g_u + (size_t)p.x * HH));
        ulonglong2 B0 = __ldg((const ulonglong2*)(g_u + (size_t)p.x * HH) + 1);
        ulonglong2 A1 = __ldg((const ulonglong2*)(g_u + (size_t)s1i * HH));
        ulonglong2 B1v = __ldg((const ulonglong2*)(g_u + (size_t)s1i * HH) + 1);
        u64 dp0 = fpack2(ds0), dp1 = fpack2(ds1);
        A0.x = fmul2(A0.x, dp0); A0.y = fmul2(A0.y, dp0);
        B0.x = fmul2(B0.x, dp0); B0.y = fmul2(B0.y, dp0);
        red_add_v4u(g_agg1 + (size_t)p.y * HH,     A0);
        red_add_v4u(g_agg1 + (size_t)p.y * HH + 4, B0);
        if (h1) {
            A1.x = fmul2(A1.x, dp1); A1.y = fmul2(A1.y, dp1);
            B1v.x = fmul2(B1v.x, dp1); B1v.y = fmul2(B1v.y, dp1);
            red_add_v4u(g_agg1 + (size_t)p.w * HH,     A1);
            red_add_v4u(g_agg1 + (size_t)p.w * HH + 4, B1v);
        }
    }
    gsync(nb);

    // ====== Phase D: self-loop + bias + LN + ReLU + dinv; seed agg2; zero agg1
    {
        float B1[HH], G[HH], BT[HH];
#pragma unroll
        for (int k = 0; k < HH; k++) {
            B1[k] = __ldg(&b1[k]); G[k] = __ldg(&gamma[k]); BT[k] = __ldg(&beta[k]);
        }
        const float4 z4 = make_float4(0.f, 0.f, 0.f, 0.f);
        for (int n = gtid; n < N; n += T) {
            float di = rsqrtf(1.0f + (float)g_degi[n]);
            float4 p0 = ((const float4*)g_agg1)[n * 2];
            float4 p1 = ((const float4*)g_agg1)[n * 2 + 1];
            float4 q0 = ((const float4*)g_u)[n * 2];
            float4 q1 = ((const float4*)g_u)[n * 2 + 1];
            float h[HH] = {p0.x, p0.y, p0.z, p0.w, p1.x, p1.y, p1.z, p1.w};
            float q[HH] = {q0.x, q0.y, q0.z, q0.w, q1.x, q1.y, q1.z, q1.w};
            float mu = 0.f;
#pragma unroll
            for (int k = 0; k < HH; k++) {
                // h = (scatters + u_raw[n]*di) * di + b1   (self-loop analytic)
                h[k] = fmaf(q[k], di, h[k]) * di + B1[k];
                mu += h[k];
            }
            mu *= 0.125f;
            float var = 0.f;
#pragma unroll
            for (int k = 0; k < HH; k++) { float d = h[k] - mu; var += d * d; }
            var *= 0.125f;
            float r = rsqrtf(var + LN_EPS);
            float v[HH];
#pragma unroll
            for (int k = 0; k < HH; k++) {
                float hn = (h[k] - mu) * r * G[k] + BT[k];
                v[k] = fmaxf(hn, 0.f) * di;
            }
            float4 o0 = make_float4(v[0], v[1], v[2], v[3]);
            float4 o1 = make_float4(v[4], v[5], v[6], v[7]);
            ((float4*)g_v)[n * 2]        = o0;
            ((float4*)g_v)[n * 2 + 1]    = o1;
            ((float4*)g_agg2)[n * 2]     = o0;   // self-loop seed (v fully scaled)
            ((float4*)g_agg2)[n * 2 + 1] = o1;
            ((float4*)g_agg1)[n * 2]     = z4;   // restore zero-invariant
            ((float4*)g_agg1)[n * 2 + 1] = z4;
        }
    }
    gsync(nb);

    // ================= Phase E: scatter agg2 += v[src]; 2 edges/thread ========
    for (int i = gtid; 2 * i < E; i += T) {
        int e0 = 2 * i;
        bool h1 = (e0 + 1 < E);
        int4 p = *(const int4*)&g_edge[e0];
        int s1i = h1 ? p.z : p.x;
        float4 a0 = __ldg((const float4*)(g_v + (size_t)p.x * HH));
        float4 b0 = __ldg((const float4*)(g_v + (size_t)p.x * HH) + 1);
        float4 a1 = __ldg((const float4*)(g_v + (size_t)s1i * HH));
        float4 b1_ = __ldg((const float4*)(g_v + (size_t)s1i * HH) + 1);
        red_add_v4(g_agg2 + (size_t)p.y * HH,     a0);
        red_add_v4(g_agg2 + (size_t)p.y * HH + 4, b0);
        if (h1) {
            red_add_v4(g_agg2 + (size_t)p.w * HH,     a1);
            red_add_v4(g_agg2 + (size_t)p.w * HH + 4, b1_);
        }
    }
    gsync(nb);

    // ============ Phase F: GEMM2 + relu + sf (weights pre-staged) =============
    for (int n0 = gwarp * 4; n0 < N; n0 += W * 4) {
        int nl = n0 + (lane >> 3); if (nl >= N) nl = N - 1;
        float di  = rsqrtf(1.0f + (float)g_degi[nl]);
        float myv = g_agg2[(size_t)nl * HH + (lane & 7)] * di;
        float sfv = sf[nl];
        float a[4][HH];
        float s[4];
#pragma unroll
        for (int i = 0; i < 4; i++) {
            s[i] = __shfl_sync(0xffffffffu, sfv, i * 8);
#pragma unroll
            for (int h = 0; h < HH; h++)
                a[i][h] = __shfl_sync(0xffffffffu, myv, i * 8 + h);
        }
#pragma unroll
        for (int j = 0; j < 4; j++) {
            int d4 = lane + 32 * j;
            ulonglong2 bias = ((const ulonglong2*)&s_w2[DD * HH])[d4];
            ulonglong2 A0 = bias, A1 = bias, A2 = bias, A3 = bias;
#pragma unroll
            for (int h = 0; h < HH; h++) {
                ulonglong2 w = ((const ulonglong2*)s_w2)[h * (DD / 4) + d4]; // LDS.128
                u64 p0 = fpack2(a[0][h]);
                u64 p1 = fpack2(a[1][h]);
                u64 p2 = fpack2(a[2][h]);
                u64 p3 = fpack2(a[3][h]);
                A0.x = ffma2(p0, w.x, A0.x);  A0.y = ffma2(p0, w.y, A0.y);
                A1.x = ffma2(p1, w.x, A1.x);  A1.y = ffma2(p1, w.y, A1.y);
                A2.x = ffma2(p2, w.x, A2.x);  A2.y = ffma2(p2, w.y, A2.y);
                A3.x = ffma2(p3, w.x, A3.x);  A3.y = ffma2(p3, w.y, A3.y);
            }
            float2 l0 = funpack2(A0.x), h0 = funpack2(A0.y);
            float2 l1 = funpack2(A1.x), h1 = funpack2(A1.y);
            float2 l2 = funpack2(A2.x), h2 = funpack2(A2.y);
            float2 l3 = funpack2(A3.x), h3 = funpack2(A3.y);
            float4 r0 = make_float4(fmaxf(l0.x,0.f)*s[0], fmaxf(l0.y,0.f)*s[0],
                                    fmaxf(h0.x,0.f)*s[0], fmaxf(h0.y,0.f)*s[0]);
            float4 r1 = make_float4(fmaxf(l1.x,0.f)*s[1], fmaxf(l1.y,0.f)*s[1],
                                    fmaxf(h1.x,0.f)*s[1], fmaxf(h1.y,0.f)*s[1]);
            float4 r2 = make_float4(fmaxf(l2.x,0.f)*s[2], fmaxf(l2.y,0.f)*s[2],
                                    fmaxf(h2.x,0.f)*s[2], fmaxf(h2.y,0.f)*s[2]);
            float4 r3 = make_float4(fmaxf(l3.x,0.f)*s[3], fmaxf(l3.y,0.f)*s[3],
                                    fmaxf(h3.x,0.f)*s[3], fmaxf(h3.y,0.f)*s[3]);
            if (n0 + 0 < N) __stcs((float4*)out + (size_t)(n0+0) * (DD/4) + d4, r0);
            if (n0 + 1 < N) __stcs((float4*)out + (size_t)(n0+1) * (DD/4) + d4, r1);
            if (n0 + 2 < N) __stcs((float4*)out + (size_t)(n0+2) * (DD/4) + d4, r2);
            if (n0 + 3 < N) __stcs((float4*)out + (size_t)(n0+3) * (DD/4) + d4, r3);
        }
        if (lane < 4 && n0 + lane < N) g_degi[n0 + lane] = 0;  // restore invariant
    }
}

// ---------------- launch -------------------------------------------------------
extern "C" void kernel_launch(void* const* d_in, const int* in_sizes, int n_in,
                              void* d_out, int out_size) {
    const float* x     = (const float*)d_in[0];
    const float* sf    = (const float*)d_in[1];
    const float* W1    = (const float*)d_in[2];
    const float* b1    = (const float*)d_in[3];
    const float* gamma = (const float*)d_in[4];
    const float* beta  = (const float*)d_in[5];
    const float* W2    = (const float*)d_in[6];
    const float* b2    = (const float*)d_in[7];
    const int*   ei    = (const int*)d_in[8];
    float* out = (float*)d_out;

    int N = in_sizes[0] / DD;
    int E = in_sizes[8] / 2;
    if (N > MAXN) N = MAXN;
    if (E > MAXE) E = MAXE;

    static int s_grid = 0;
    if (s_grid == 0) {
        int nsm = 0, bps = 0;
        cudaDeviceGetAttribute(&nsm, cudaDevAttrMultiProcessorCount, 0);
        cudaOccupancyMaxActiveBlocksPerMultiprocessor(&bps, k_fused, TPB, 0);
        if (nsm <= 0) nsm = 148;
        if (bps <= 0) bps = 2;
        s_grid = nsm * bps;
    }
    unsigned nb = (unsigned)s_grid;
    k_fused<<<s_grid, TPB>>>(x, sf, W1, b1, gamma, beta, W2, b2, ei, out,
                             N, E, nb);
}